// round 7
// baseline (speedup 1.0000x reference)
#include <cuda_runtime.h>
#include <cstdint>

// Problem constants
#define EE 130                     // 2*D + 2
#define HE 1040                    // H*E
#define NTOK 32768                 // B*N
#define TENSOR_ELEMS (NTOK * HE)

#define TT 32                      // tokens per tile
#define NTILES_T 1024              // tiles per type (NTOK/TT)
#define THREADS 256
#define CTAS_PER_TYPE 74
#define GRID (4 * CTAS_PER_TYPE)   // 296 = 2 CTAs/SM * 148 SMs
#define NWARPS_G (GRID * 8)        // 2368 global warps
#define AUX_ROWS (3 * NTOK)        // 98304 (tensor, token) rows

#define MAT_STRIDE 4100            // 64*64 + 4 pad
#define WSM_FLOATS (4 * MAT_STRIDE)
#define XS_FLOATS (TT * 64)
#define SMEM_BYTES ((WSM_FLOATS + XS_FLOATS) * 4)   // 73,792 B -> 2 CTAs/SM

__device__ __forceinline__ double fma2(double a, double b, double c) {
    double d;
    asm("fma.rn.f32x2 %0, %1, %2, %3;" : "=d"(d) : "d"(a), "d"(b), "d"(c));
    return d;
}
__device__ __forceinline__ float pair_sum(double a) {
    return __int_as_float(__double2loint(a)) + __int_as_float(__double2hiint(a));
}

extern __shared__ float smem[];

// Aux row r in [0, 98304): tau = r/NTOK (0=q,1=k,2=v), t = r%NTOK.
// Writes every non-computed element of that (tensor, token) row.
// Zero spans start at even offsets -> STG.64 always 8B-aligned.
__device__ __forceinline__ void do_aux_row(int r, const float* __restrict__ x,
                                           float* __restrict__ out,
                                           float bq, float bk, int lane)
{
    const float2 z2 = make_float2(0.f, 0.f);
    int tau = r / NTOK;
    int t   = r - tau * NTOK;
    float* row = out + (size_t)tau * TENSOR_ELEMS + (size_t)t * HE;
    if (tau < 2) {
        #pragma unroll
        for (int h = 0; h < 8; ++h) {           // zeros [0,65): 32xSTG.64 + tail
            float* base = row + h * 130;
            *(float2*)(base + 2 * lane) = z2;
            if (lane == 0) base[64] = 0.f;
        }
        #pragma unroll
        for (int h = 4; h < 8; ++h) {           // heads 4-7: zeros [66,130)
            float* base = row + h * 130 + 66;
            *(float2*)(base + 2 * lane) = z2;
        }
        if (lane < 8) {                          // scalar outputs
            const float* xr = x + (size_t)t * EE;
            float s, bv; int pos;
            if (tau == 0) { bv = bq; s = xr[129]; pos = (lane < 4) ? 129 : 65; }
            else {
                bv = bk;
                if (lane < 4) { s = xr[129]; pos = 129; }
                else          { s = xr[64];  pos = 65;  }
            }
            row[lane * 130 + pos] = s * bv;
        }
    } else {
        #pragma unroll
        for (int h = 0; h < 8; ++h) {           // v: zeros [0,65) and {129}
            float* base = row + h * 130;
            *(float2*)(base + 2 * lane) = z2;
            if (lane == 0) { base[64] = 0.f; base[129] = 0.f; }
        }
    }
}

// CTA types: 0=Q (M_q, x2), 1=K (M_k, x1), 2=V h0-3 (x1), 3=V h4-7 (x1)
__global__ __launch_bounds__(THREADS, 2)
void qkv_kernel(const float* __restrict__ x,
                const float* __restrict__ Mq,
                const float* __restrict__ Bq,
                const float* __restrict__ Mk,
                const float* __restrict__ Bk,
                const float* __restrict__ Mv,
                float* __restrict__ out)
{
    const int type = blockIdx.x & 3;
    const int cta  = blockIdx.x >> 2;       // 0..73 within type
    const int tid  = threadIdx.x;
    const int warp = tid >> 5, lane = tid & 31;

    float* wsm = smem;
    float* xs  = smem + WSM_FLOATS;

    // ---- Stage 4 weight matrices ONCE (float4 LDG -> swizzled float4 STS) ----
    const float* wsrc = (type == 0) ? Mq
                      : (type == 1) ? Mk
                      : (type == 2) ? Mv
                      :               (Mv + 4 * 4096);
    for (int idx = tid; idx < 4 * 1024; idx += THREADS) {
        int mat = idx >> 10;
        int r4  = idx & 1023;
        int i   = r4 >> 4;             // output row of M (= compute "col")
        int kp0 = (r4 & 15) * 2;       // first k-pair (even)
        float4 v = ((const float4*)(wsrc + mat * 4096))[r4];
        int s0 = (kp0 + 2 * (i & 7)) & 31;
        *(float4*)(wsm + mat * MAT_STRIDE + i * 64 + s0 * 2) = v;
    }

    // Per-lane bias values for aux scalar writes (lane<8 uses them)
    const float bq = (lane < 8) ? Bq[lane] : 0.f;
    const float bk = (lane < 8) ? Bk[lane] : 0.f;

    // Aux iterator: global warp id strided over the flat row space
    int arow = blockIdx.x * 8 + warp;

    // Compute-lane decomposition
    const int tokG   = warp >> 1;
    const int half   = warp & 1;
    const int mi     = lane >> 3;
    const int colSub = lane & 7;
    const int myTok0 = tokG * 8;
    const int xoff   = (type == 0) ? 65 : 0;

    float* T;
    int h;
    if (type == 0)      { T = out;                              h = mi; }
    else if (type == 1) { T = out + (size_t)TENSOR_ELEMS;       h = mi; }
    else                { T = out + (size_t)2 * TENSOR_ELEMS;   h = ((type == 2) ? 0 : 4) + mi; }

    const float* wrow0 = wsm + mi * MAT_STRIDE + (colSub + 32 * half) * 64;
    const float* xbase = xs + myTok0 * 64;

    // ---- Persistent tile loop ----
    for (int tile = cta; tile < NTILES_T; tile += CTAS_PER_TYPE) {
        const int tok0 = tile * TT;
        __syncthreads();   // x buffer free (prev compute done; also orders weight staging)

        // stage x slice (Q: x2 = x[65:129], else x1)
        for (int idx = tid; idx < TT * 64; idx += THREADS) {
            int t = idx >> 6, e = idx & 63;
            xs[idx] = x[(size_t)(tok0 + t) * EE + xoff + e];
        }

        // aux rows: up to 3 per warp per tile-iter, overlapping the x-stage latency
        #pragma unroll
        for (int a = 0; a < 3; ++a) {
            if (arow < AUX_ROWS) { do_aux_row(arow, x, out, bq, bk, lane); arow += NWARPS_G; }
        }

        __syncthreads();

        // ---- pipelined compute: 16 iters of 2 k-pairs ----
        double acc[8][4];
        #pragma unroll
        for (int i = 0; i < 8; ++i)
            #pragma unroll
            for (int j = 0; j < 4; ++j) acc[i][j] = 0.0;

        double2 xp[8], wp[4];
        #pragma unroll
        for (int i = 0; i < 8; ++i) xp[i] = *(const double2*)(xbase + i * 64);
        {
            const int s = (2 * colSub) & 31;
            #pragma unroll
            for (int j = 0; j < 4; ++j) wp[j] = *(const double2*)(wrow0 + j * 512 + s * 2);
        }

        #pragma unroll 3
        for (int it = 0; it < 15; ++it) {
            #pragma unroll
            for (int i = 0; i < 8; ++i) {
                #pragma unroll
                for (int j = 0; j < 4; ++j) {
                    acc[i][j] = fma2(xp[i].x, wp[j].x, acc[i][j]);
                    acc[i][j] = fma2(xp[i].y, wp[j].y, acc[i][j]);
                }
                xp[i] = *(const double2*)(xbase + i * 64 + 4 * (it + 1));  // prefetch next
            }
            const int s = (2 * (it + 1) + 2 * colSub) & 31;
            #pragma unroll
            for (int j = 0; j < 4; ++j)
                wp[j] = *(const double2*)(wrow0 + j * 512 + s * 2);        // prefetch next
        }
        #pragma unroll
        for (int i = 0; i < 8; ++i)
            #pragma unroll
            for (int j = 0; j < 4; ++j) {
                acc[i][j] = fma2(xp[i].x, wp[j].x, acc[i][j]);
                acc[i][j] = fma2(xp[i].y, wp[j].y, acc[i][j]);
            }

        // ---- epilogue: computed outputs ----
        #pragma unroll
        for (int i = 0; i < 8; ++i) {
            float* o = T + (size_t)(tok0 + myTok0 + i) * HE + h * 130 + 65 + 32 * half + colSub;
            #pragma unroll
            for (int j = 0; j < 4; ++j)
                o[8 * j] = pair_sum(acc[i][j]);
        }
    }

    // drain remaining aux rows
    while (arow < AUX_ROWS) { do_aux_row(arow, x, out, bq, bk, lane); arow += NWARPS_G; }
}

extern "C" void kernel_launch(void* const* d_in, const int* in_sizes, int n_in,
                              void* d_out, int out_size) {
    const float* x  = (const float*)d_in[0];
    const float* Mq = (const float*)d_in[1];
    const float* Bq = (const float*)d_in[2];
    const float* Mk = (const float*)d_in[3];
    const float* Bk = (const float*)d_in[4];
    const float* Mv = (const float*)d_in[5];
    float* out = (float*)d_out;

    cudaFuncSetAttribute(qkv_kernel, cudaFuncAttributeMaxDynamicSharedMemorySize, SMEM_BYTES);
    qkv_kernel<<<GRID, THREADS, SMEM_BYTES>>>(x, Mq, Bq, Bk ? Mk : Mk, Bk, Mv, out);
}